// round 8
// baseline (speedup 1.0000x reference)
#include <cuda_runtime.h>
#include <cuda_fp16.h>

// Problem constants (LightGCN_56538949484988)
#define NN 50000           // nodes
#define EE 800000          // edges
#define B_MAX 4096
#define ROWS7_MAX (7 * B_MAX)

// ---------------- device scratch (no allocations allowed) ----------------
__device__ int    g_is32;
__device__ int    g_scan_done;
__device__ int    g_deg[NN];       // zero-initialized; re-zeroed by last prop layer
__device__ int    g_off[NN];
__device__ int    g_cur[NN];
__device__ int    g_col[EE];
__device__ float  g_dinv[NN];
__device__ float  g_sdeg[NN];
__device__ int    g_bsum[64];
// u_k = dinv^2 * gathered-sum, fp16. 16 uint4 (=128 halves) per node.
__device__ uint4  g_u0[NN * 16];
__device__ uint4  g_u1[NN * 16];
__device__ uint4  g_u2[NN * 16];
__device__ uint4  g_u3[NN * 16];
// head phase-1 output: t[i] = z_i @ W1half (fp32, 128/row)
__device__ float4 g_t[ROWS7_MAX * 32];

__device__ __forceinline__ int ld_idx(const void* p, long long i, int is32) {
    if (is32) return ((const int*)p)[i];
    return (int)((const long long*)p)[i];
}

__device__ __forceinline__ uint4 pack8h(const float* f) {
    __half2 h0 = __floats2half2_rn(f[0], f[1]);
    __half2 h1 = __floats2half2_rn(f[2], f[3]);
    __half2 h2 = __floats2half2_rn(f[4], f[5]);
    __half2 h3 = __floats2half2_rn(f[6], f[7]);
    uint4 r;
    r.x = *reinterpret_cast<unsigned*>(&h0);
    r.y = *reinterpret_cast<unsigned*>(&h1);
    r.z = *reinterpret_cast<unsigned*>(&h2);
    r.w = *reinterpret_cast<unsigned*>(&h3);
    return r;
}

// ---- packed fp32x2 (Blackwell PTX) ----
__device__ __forceinline__ unsigned long long pack2(float a, float b) {
    unsigned long long r;
    asm("mov.b64 %0, {%1, %2};" : "=l"(r) : "f"(a), "f"(b));
    return r;
}
__device__ __forceinline__ unsigned long long add2(unsigned long long a,
                                                   unsigned long long b) {
    unsigned long long d;
    asm("add.rn.f32x2 %0, %1, %2;" : "=l"(d) : "l"(a), "l"(b));
    return d;
}
__device__ __forceinline__ unsigned long long fma2(unsigned long long a,
                                                   unsigned long long b,
                                                   unsigned long long c) {
    unsigned long long d;
    asm("fma.rn.f32x2 %0, %1, %2, %3;" : "=l"(d) : "l"(a), "l"(b), "l"(c));
    return d;
}
__device__ __forceinline__ float2 unpack2(unsigned long long v) {
    float x, y;
    asm("mov.b64 {%0, %1}, %2;" : "=f"(x), "=f"(y) : "l"(v));
    return make_float2(x, y);
}
__device__ __forceinline__ unsigned long long h2f2(__half2 h) {
    float2 f = __half22float2(h);
    return pack2(f.x, f.y);
}
#define H2REF(u) (*reinterpret_cast<__half2*>(&(u)))

// ---- hist (+inline dtype detect, + reset scan counter) ----
__global__ __launch_bounds__(256) void hist_kernel(const void* __restrict__ eidx, int E) {
    __shared__ int sflag;
    int t = threadIdx.x;
    if (t == 0) sflag = 0;
    __syncthreads();
    if (t < 64) {
        long long v = ((const long long*)eidx)[t];
        if (v < 0 || v >= (long long)NN) sflag = 1;   // benign race
    }
    __syncthreads();
    int is32 = sflag;
    if (blockIdx.x == 0 && t == 0) { g_is32 = is32; g_scan_done = 0; }
    int e = blockIdx.x * blockDim.x + t;
    if (e >= E) return;
    int r = ld_idx(eidx, e, is32);
    atomicAdd(&g_deg[r], 1);
}

// ---- fused 3-phase scan: one kernel, <=64 co-resident blocks ----
__global__ __launch_bounds__(256) void scan_fused_kernel(int N, int nblk) {
    __shared__ int wsum[8];
    __shared__ int sred[2];
    int bid = blockIdx.x, t = threadIdx.x;
    int i0 = bid * 1024 + t * 4;
    int d0 = 0, d1 = 0, d2 = 0, d3 = 0;
    if (i0 + 0 < N) d0 = g_deg[i0 + 0];
    if (i0 + 1 < N) d1 = g_deg[i0 + 1];
    if (i0 + 2 < N) d2 = g_deg[i0 + 2];
    if (i0 + 3 < N) d3 = g_deg[i0 + 3];
    int tsum = d0 + d1 + d2 + d3;
    int lane = t & 31, w = t >> 5;
    int x = tsum;
#pragma unroll
    for (int o = 1; o < 32; o <<= 1) {
        int y = __shfl_up_sync(0xffffffffu, x, o);
        if (lane >= o) x += y;
    }
    if (lane == 31) wsum[w] = x;
    __syncthreads();
    int wpref = 0, btotal = 0;
#pragma unroll
    for (int j = 0; j < 8; j++) {
        int v = wsum[j];
        if (j < w) wpref += v;
        btotal += v;
    }
    if (t == 0) {
        g_bsum[bid] = btotal;
        __threadfence();
        atomicAdd(&g_scan_done, 1);
        while (*(volatile int*)&g_scan_done < nblk) { }
    }
    __syncthreads();
    int pv = (t < 64 && t < bid) ? __ldcg(&g_bsum[t]) : 0;
    if (t < 64) {
#pragma unroll
        for (int o = 16; o; o >>= 1) pv += __shfl_xor_sync(0xffffffffu, pv, o);
        if ((t & 31) == 0) sred[t >> 5] = pv;
    }
    __syncthreads();
    int boff = sred[0] + sred[1];
    int excl = x - tsum + wpref + boff;
    int o0 = excl, o1 = o0 + d0, o2 = o1 + d1, o3 = o2 + d2;
#define EMIT(ii, oo, dd) \
    if (ii < N) { g_off[ii] = oo; g_cur[ii] = oo; \
        g_dinv[ii] = (dd) > 0 ? rsqrtf((float)(dd)) : 0.f; \
        g_sdeg[ii] = sqrtf((float)(dd)); }
    EMIT(i0 + 0, o0, d0)
    EMIT(i0 + 1, o1, d1)
    EMIT(i0 + 2, o2, d2)
    EMIT(i0 + 3, o3, d3)
#undef EMIT
}

// ---- fused scatter (CSR fill) + init (u0 = fp16(dinv .* emb)) ----
__global__ __launch_bounds__(256) void scatter_init_kernel(
    const void* __restrict__ eidx, const float4* __restrict__ emb, int E, int N16)
{
    int i = blockIdx.x * blockDim.x + threadIdx.x;
    int is32 = g_is32;
    if (i < E) {
        int r = ld_idx(eidx, i, is32);
        int c = ld_idx(eidx, (long long)E + i, is32);
        int p = atomicAdd(&g_cur[r], 1);
        g_col[p] = c;
    }
    if (i < N16) {
        int node = i >> 4, p = i & 15;
        float4 a = emb[node * 32 + p * 2];
        float4 b = emb[node * 32 + p * 2 + 1];
        float di = g_dinv[node];
        float f[8] = { a.x * di, a.y * di, a.z * di, a.w * di,
                       b.x * di, b.y * di, b.z * di, b.w * di };
        g_u0[i] = pack8h(f);
    }
}

// ---- one propagation layer: warp/node; half-warps own contiguous halves of
// the edge range; 4 edges/iter with independent loads (MLP=4) and a
// 2-level HADD2 tree before fp32 conversion. ----
__global__ __launch_bounds__(256) void prop_kernel(int layer, int N, int zero_deg) {
    int gw   = (blockIdx.x * blockDim.x + threadIdx.x) >> 5;
    int lane = threadIdx.x & 31;
    if (gw >= N) return;
    const uint4* __restrict__ uin  = (layer == 0) ? g_u0 : (layer == 1) ? g_u1 : g_u2;
    uint4* __restrict__       uout = (layer == 0) ? g_u1 : (layer == 1) ? g_u2 : g_u3;
    int start = g_off[gw];
    int d     = g_deg[gw];
    int half  = lane >> 4;
    int l16   = lane & 15;
    int mid   = start + (d >> 1);
    int s0 = half ? mid : start;
    int e0 = half ? (start + d) : mid;

    unsigned long long acc0 = 0ull, acc1 = 0ull, acc2 = 0ull, acc3 = 0ull;
    int e = s0;
    for (; e + 3 < e0; e += 4) {
        int c0 = __ldg(&g_col[e]);
        int c1 = __ldg(&g_col[e + 1]);
        int c2 = __ldg(&g_col[e + 2]);
        int c3 = __ldg(&g_col[e + 3]);
        uint4 v0 = __ldg(&uin[c0 * 16 + l16]);
        uint4 v1 = __ldg(&uin[c1 * 16 + l16]);
        uint4 v2 = __ldg(&uin[c2 * 16 + l16]);
        uint4 v3 = __ldg(&uin[c3 * 16 + l16]);
        __half2 q0 = __hadd2(__hadd2(H2REF(v0.x), H2REF(v1.x)),
                             __hadd2(H2REF(v2.x), H2REF(v3.x)));
        __half2 q1 = __hadd2(__hadd2(H2REF(v0.y), H2REF(v1.y)),
                             __hadd2(H2REF(v2.y), H2REF(v3.y)));
        __half2 q2 = __hadd2(__hadd2(H2REF(v0.z), H2REF(v1.z)),
                             __hadd2(H2REF(v2.z), H2REF(v3.z)));
        __half2 q3 = __hadd2(__hadd2(H2REF(v0.w), H2REF(v1.w)),
                             __hadd2(H2REF(v2.w), H2REF(v3.w)));
        acc0 = add2(acc0, h2f2(q0));
        acc1 = add2(acc1, h2f2(q1));
        acc2 = add2(acc2, h2f2(q2));
        acc3 = add2(acc3, h2f2(q3));
    }
    if (e + 1 < e0) {
        int c0 = __ldg(&g_col[e]);
        int c1 = __ldg(&g_col[e + 1]);
        uint4 v0 = __ldg(&uin[c0 * 16 + l16]);
        uint4 v1 = __ldg(&uin[c1 * 16 + l16]);
        acc0 = add2(acc0, h2f2(__hadd2(H2REF(v0.x), H2REF(v1.x))));
        acc1 = add2(acc1, h2f2(__hadd2(H2REF(v0.y), H2REF(v1.y))));
        acc2 = add2(acc2, h2f2(__hadd2(H2REF(v0.z), H2REF(v1.z))));
        acc3 = add2(acc3, h2f2(__hadd2(H2REF(v0.w), H2REF(v1.w))));
        e += 2;
    }
    if (e < e0) {
        int c0 = __ldg(&g_col[e]);
        uint4 v0 = __ldg(&uin[c0 * 16 + l16]);
        acc0 = add2(acc0, h2f2(H2REF(v0.x)));
        acc1 = add2(acc1, h2f2(H2REF(v0.y)));
        acc2 = add2(acc2, h2f2(H2REF(v0.z)));
        acc3 = add2(acc3, h2f2(H2REF(v0.w)));
    }

    float2 f0 = unpack2(acc0);
    float2 f1 = unpack2(acc1);
    float2 f2 = unpack2(acc2);
    float2 f3 = unpack2(acc3);
    float a[8] = { f0.x, f0.y, f1.x, f1.y, f2.x, f2.y, f3.x, f3.y };
#pragma unroll
    for (int i = 0; i < 8; i++) a[i] += __shfl_xor_sync(0xffffffffu, a[i], 16);
    float di = g_dinv[gw];
    float s = di * di;
    if (half == 0) {
        float f[8];
#pragma unroll
        for (int i = 0; i < 8; i++) f[i] = s * a[i];
        uout[gw * 16 + l16] = pack8h(f);
    }
    if (zero_deg && lane == 0) g_deg[gw] = 0;   // restore invariant for next replay
}

// ---- head phase 1: t[i] = z_i @ W1half, 4 rows/warp, f32x2 FMAs.
// z values duplicated as (z,z) u64 in smem; k-loop does LDS broadcast + 2 fma2
// per (row,k). W row loaded once per k as ulonglong2 (LDG.128). ----
__global__ __launch_bounds__(256) void head1_kernel(
    const void* __restrict__ nid,
    const float4* __restrict__ emb,
    const float* __restrict__ w1,      // (256,128) row-major
    int b, int rows7)
{
    __shared__ unsigned long long sz[8 * 4 * 128];   // 32 KB: [warp][row][k]
    int lane = threadIdx.x & 31;
    int wib  = threadIdx.x >> 5;                     // warp in block
    int warp = (blockIdx.x * blockDim.x + threadIdx.x) >> 5;
    int row0 = warp * 4;
    if (row0 >= rows7) return;
    int is32 = g_is32;
    int nvalid = min(4, rows7 - row0);
    unsigned long long* szw = sz + wib * 512;

    const uint2* u1v = reinterpret_cast<const uint2*>(g_u1);
    const uint2* u2v = reinterpret_cast<const uint2*>(g_u2);
    const uint2* u3v = reinterpret_cast<const uint2*>(g_u3);

    int koffr[4];
#pragma unroll
    for (int r = 0; r < 4; r++) {
        int row = row0 + ((r < nvalid) ? r : (nvalid - 1));
        koffr[r] = (row < b) ? 0 : 128;
        int node = ld_idx(nid, row, is32);
        float4 e = __ldg(&emb[node * 32 + lane]);
        uint2 v1 = __ldg(&u1v[node * 32 + lane]);
        uint2 v2 = __ldg(&u2v[node * 32 + lane]);
        uint2 v3 = __ldg(&u3v[node * 32 + lane]);
        float sd = __ldg(&g_sdeg[node]);
        float2 a0 = __half22float2(H2REF(v1.x));
        float2 a1 = __half22float2(H2REF(v1.y));
        float2 b0 = __half22float2(H2REF(v2.x));
        float2 b1_ = __half22float2(H2REF(v2.y));
        float2 c0 = __half22float2(H2REF(v3.x));
        float2 c1 = __half22float2(H2REF(v3.y));
        float z0 = 0.25f * (e.x + sd * (a0.x + b0.x + c0.x));
        float z1 = 0.25f * (e.y + sd * (a0.y + b0.y + c0.y));
        float z2 = 0.25f * (e.z + sd * (a1.x + b1_.x + c1.x));
        float z3 = 0.25f * (e.w + sd * (a1.y + b1_.y + c1.y));
        szw[r * 128 + lane * 4 + 0] = pack2(z0, z0);
        szw[r * 128 + lane * 4 + 1] = pack2(z1, z1);
        szw[r * 128 + lane * 4 + 2] = pack2(z2, z2);
        szw[r * 128 + lane * 4 + 3] = pack2(z3, z3);
    }
    __syncwarp();

    unsigned long long acc[4][2];
#pragma unroll
    for (int r = 0; r < 4; r++) { acc[r][0] = 0ull; acc[r][1] = 0ull; }

    const ulonglong2* wll = reinterpret_cast<const ulonglong2*>(w1);
    bool uni = (koffr[0] == koffr[3]);

    if (uni) {
        int koff = koffr[0];
#pragma unroll 4
        for (int k = 0; k < 128; k++) {
            ulonglong2 wv = __ldg(&wll[(koff + k) * 32 + lane]);
#pragma unroll
            for (int r = 0; r < 4; r++) {
                unsigned long long z2 = szw[r * 128 + k];
                acc[r][0] = fma2(wv.x, z2, acc[r][0]);
                acc[r][1] = fma2(wv.y, z2, acc[r][1]);
            }
        }
    } else {
#pragma unroll 2
        for (int k = 0; k < 128; k++) {
#pragma unroll
            for (int r = 0; r < 4; r++) {
                ulonglong2 wv = __ldg(&wll[(koffr[r] + k) * 32 + lane]);
                unsigned long long z2 = szw[r * 128 + k];
                acc[r][0] = fma2(wv.x, z2, acc[r][0]);
                acc[r][1] = fma2(wv.y, z2, acc[r][1]);
            }
        }
    }

#pragma unroll
    for (int r = 0; r < 4; r++) {
        if (r >= nvalid) break;
        float2 a0 = unpack2(acc[r][0]);
        float2 a1 = unpack2(acc[r][1]);
        // lane covers output cols lane*4 .. lane*4+3 -> float4 at index lane
        g_t[(row0 + r) * 32 + lane] = make_float4(a0.x, a0.y, a1.x, a1.y);
    }
}

// ---- head phase 2: combine t rows -> logits ----
__global__ __launch_bounds__(256) void head2_kernel(
    const float* __restrict__ b1,
    const float* __restrict__ w2,
    const float* __restrict__ b2,
    float* __restrict__ out,
    int b, int total)
{
    int lane = threadIdx.x & 31;
    int warp = (blockIdx.x * blockDim.x + threadIdx.x) >> 5;
    int row0 = warp * 4;
    if (row0 >= total) return;
    float4 b1v = __ldg((const float4*)b1 + lane);
    float4 w2v = __ldg((const float4*)w2 + lane);
    float bias2 = __ldg(b2);
    int nvalid = min(4, total - row0);
    for (int r = 0; r < nvalid; r++) {
        int row = row0 + r;
        int i1, i2;
        if (row < b) { i1 = row; i2 = b + row; }
        else { int j = row - b; i1 = j / 5; i2 = 2 * b + j; }
        float4 ta = __ldg(&g_t[i1 * 32 + lane]);
        float4 tb = __ldg(&g_t[i2 * 32 + lane]);
        float4 h;
        h.x = ta.x + tb.x + b1v.x;
        h.y = ta.y + tb.y + b1v.y;
        h.z = ta.z + tb.z + b1v.z;
        h.w = ta.w + tb.w + b1v.w;
        h.x = (h.x > 0.f) ? h.x : 0.2f * h.x;
        h.y = (h.y > 0.f) ? h.y : 0.2f * h.y;
        h.z = (h.z > 0.f) ? h.z : 0.2f * h.z;
        h.w = (h.w > 0.f) ? h.w : 0.2f * h.w;
        float p = h.x * w2v.x + h.y * w2v.y + h.z * w2v.z + h.w * w2v.w;
#pragma unroll
        for (int off = 16; off; off >>= 1) p += __shfl_xor_sync(0xffffffffu, p, off);
        if (lane == 0) out[row] = p + bias2;
    }
}

extern "C" void kernel_launch(void* const* d_in, const int* in_sizes, int n_in,
                              void* d_out, int out_size) {
    // Order: x, edge_index, edge_weight, n_id, [neg_sample_num], id_embed, w1, b1, w2, b2
    const void* eidx = d_in[1];
    int E = in_sizes[1] / 2;
    const void* nid = d_in[3];
    int base = (n_in >= 10) ? 5 : 4;
    const float* emb = (const float*)d_in[base];
    const float* w1  = (const float*)d_in[base + 1];
    const float* b1  = (const float*)d_in[base + 2];
    const float* w2  = (const float*)d_in[base + 3];
    const float* b2  = (const float*)d_in[base + 4];
    int N = in_sizes[base] / 128;
    int b = in_sizes[3] / 7;
    if (b > B_MAX) b = B_MAX;
    int rows7 = b * 7;
    int total = b * 6;
    float* out = (float*)d_out;
    (void)out_size;

    if (N > NN) N = NN;
    if (E > EE) E = EE;

    int nblk = (N + 1023) / 1024;      // <= 49 (co-resident on 148 SMs)
    int n16 = N * 16;
    int simax = (E > n16) ? E : n16;

    hist_kernel<<<(E + 255) / 256, 256>>>(eidx, E);
    scan_fused_kernel<<<nblk, 256>>>(N, nblk);
    scatter_init_kernel<<<(simax + 255) / 256, 256>>>(eidx, (const float4*)emb, E, n16);

    for (int layer = 0; layer < 3; layer++) {
        prop_kernel<<<(N + 7) / 8, 256>>>(layer, N, layer == 2);
    }

    int h1blocks = ((rows7 + 3) / 4 + 7) / 8;
    head1_kernel<<<h1blocks, 256>>>(nid, (const float4*)emb, w1, b, rows7);
    int h2blocks = ((total + 3) / 4 + 7) / 8;
    head2_kernel<<<h2blocks, 256>>>(b1, w2, b2, out, b, total);
}

// round 9
// speedup vs baseline: 1.0761x; 1.0761x over previous
#include <cuda_runtime.h>
#include <cuda_fp16.h>

// Problem constants (LightGCN_56538949484988)
#define NN 50000           // nodes
#define EE 800000          // edges
#define B_MAX 4096
#define ROWS7_MAX (7 * B_MAX)

// ---------------- device scratch (no allocations allowed) ----------------
__device__ int    g_is32;
__device__ int    g_scan_done;
__device__ int    g_deg[NN];       // zero-initialized; re-zeroed by last prop layer
__device__ int    g_off[NN];
__device__ int    g_cur[NN];
__device__ int    g_col[EE];
__device__ float  g_dinv[NN];
__device__ float  g_sdeg[NN];
__device__ int    g_bsum[64];
// u_k = dinv^2 * gathered-sum, fp16. 16 uint4 (=128 halves) per node.
__device__ uint4  g_u0[NN * 16];
__device__ uint4  g_u1[NN * 16];
__device__ uint4  g_u2[NN * 16];
__device__ uint4  g_u3[NN * 16];
// head phase-1 output: t[i] = z_i @ W1half (fp32, 128/row)
__device__ float4 g_t[ROWS7_MAX * 32];

__device__ __forceinline__ int ld_idx(const void* p, long long i, int is32) {
    if (is32) return ((const int*)p)[i];
    return (int)((const long long*)p)[i];
}

__device__ __forceinline__ uint4 pack8h(const float* f) {
    __half2 h0 = __floats2half2_rn(f[0], f[1]);
    __half2 h1 = __floats2half2_rn(f[2], f[3]);
    __half2 h2 = __floats2half2_rn(f[4], f[5]);
    __half2 h3 = __floats2half2_rn(f[6], f[7]);
    uint4 r;
    r.x = *reinterpret_cast<unsigned*>(&h0);
    r.y = *reinterpret_cast<unsigned*>(&h1);
    r.z = *reinterpret_cast<unsigned*>(&h2);
    r.w = *reinterpret_cast<unsigned*>(&h3);
    return r;
}

// ---- packed fp32x2 (Blackwell PTX) ----
__device__ __forceinline__ unsigned long long pack2(float a, float b) {
    unsigned long long r;
    asm("mov.b64 %0, {%1, %2};" : "=l"(r) : "f"(a), "f"(b));
    return r;
}
__device__ __forceinline__ unsigned long long add2(unsigned long long a,
                                                   unsigned long long b) {
    unsigned long long d;
    asm("add.rn.f32x2 %0, %1, %2;" : "=l"(d) : "l"(a), "l"(b));
    return d;
}
__device__ __forceinline__ unsigned long long fma2(unsigned long long a,
                                                   unsigned long long b,
                                                   unsigned long long c) {
    unsigned long long d;
    asm("fma.rn.f32x2 %0, %1, %2, %3;" : "=l"(d) : "l"(a), "l"(b), "l"(c));
    return d;
}
__device__ __forceinline__ float2 unpack2(unsigned long long v) {
    float x, y;
    asm("mov.b64 {%0, %1}, %2;" : "=f"(x), "=f"(y) : "l"(v));
    return make_float2(x, y);
}
__device__ __forceinline__ unsigned long long h2f2(__half2 h) {
    float2 f = __half22float2(h);
    return pack2(f.x, f.y);
}
#define H2REF(u) (*reinterpret_cast<__half2*>(&(u)))

// ---- hist (+inline dtype detect, + reset scan counter) ----
__global__ __launch_bounds__(256) void hist_kernel(const void* __restrict__ eidx, int E) {
    __shared__ int sflag;
    int t = threadIdx.x;
    if (t == 0) sflag = 0;
    __syncthreads();
    if (t < 64) {
        long long v = ((const long long*)eidx)[t];
        if (v < 0 || v >= (long long)NN) sflag = 1;   // benign race
    }
    __syncthreads();
    int is32 = sflag;
    if (blockIdx.x == 0 && t == 0) { g_is32 = is32; g_scan_done = 0; }
    int e = blockIdx.x * blockDim.x + t;
    if (e >= E) return;
    int r = ld_idx(eidx, e, is32);
    atomicAdd(&g_deg[r], 1);
}

// ---- fused 3-phase scan: one kernel, <=64 co-resident blocks ----
__global__ __launch_bounds__(256) void scan_fused_kernel(int N, int nblk) {
    __shared__ int wsum[8];
    __shared__ int sred[2];
    int bid = blockIdx.x, t = threadIdx.x;
    int i0 = bid * 1024 + t * 4;
    int d0 = 0, d1 = 0, d2 = 0, d3 = 0;
    if (i0 + 0 < N) d0 = g_deg[i0 + 0];
    if (i0 + 1 < N) d1 = g_deg[i0 + 1];
    if (i0 + 2 < N) d2 = g_deg[i0 + 2];
    if (i0 + 3 < N) d3 = g_deg[i0 + 3];
    int tsum = d0 + d1 + d2 + d3;
    int lane = t & 31, w = t >> 5;
    int x = tsum;
#pragma unroll
    for (int o = 1; o < 32; o <<= 1) {
        int y = __shfl_up_sync(0xffffffffu, x, o);
        if (lane >= o) x += y;
    }
    if (lane == 31) wsum[w] = x;
    __syncthreads();
    int wpref = 0, btotal = 0;
#pragma unroll
    for (int j = 0; j < 8; j++) {
        int v = wsum[j];
        if (j < w) wpref += v;
        btotal += v;
    }
    if (t == 0) {
        g_bsum[bid] = btotal;
        __threadfence();
        atomicAdd(&g_scan_done, 1);
        while (*(volatile int*)&g_scan_done < nblk) { }
    }
    __syncthreads();
    int pv = (t < 64 && t < bid) ? __ldcg(&g_bsum[t]) : 0;
    if (t < 64) {
#pragma unroll
        for (int o = 16; o; o >>= 1) pv += __shfl_xor_sync(0xffffffffu, pv, o);
        if ((t & 31) == 0) sred[t >> 5] = pv;
    }
    __syncthreads();
    int boff = sred[0] + sred[1];
    int excl = x - tsum + wpref + boff;
    int o0 = excl, o1 = o0 + d0, o2 = o1 + d1, o3 = o2 + d2;
#define EMIT(ii, oo, dd) \
    if (ii < N) { g_off[ii] = oo; g_cur[ii] = oo; \
        g_dinv[ii] = (dd) > 0 ? rsqrtf((float)(dd)) : 0.f; \
        g_sdeg[ii] = sqrtf((float)(dd)); }
    EMIT(i0 + 0, o0, d0)
    EMIT(i0 + 1, o1, d1)
    EMIT(i0 + 2, o2, d2)
    EMIT(i0 + 3, o3, d3)
#undef EMIT
}

// ---- fused scatter (CSR fill) + init (u0 = fp16(dinv .* emb)) ----
__global__ __launch_bounds__(256) void scatter_init_kernel(
    const void* __restrict__ eidx, const float4* __restrict__ emb, int E, int N16)
{
    int i = blockIdx.x * blockDim.x + threadIdx.x;
    int is32 = g_is32;
    if (i < E) {
        int r = ld_idx(eidx, i, is32);
        int c = ld_idx(eidx, (long long)E + i, is32);
        int p = atomicAdd(&g_cur[r], 1);
        g_col[p] = c;
    }
    if (i < N16) {
        int node = i >> 4, p = i & 15;
        float4 a = emb[node * 32 + p * 2];
        float4 b = emb[node * 32 + p * 2 + 1];
        float di = g_dinv[node];
        float f[8] = { a.x * di, a.y * di, a.z * di, a.w * di,
                       b.x * di, b.y * di, b.z * di, b.w * di };
        g_u0[i] = pack8h(f);
    }
}

// ---- one propagation layer (R6-proven): warp/node; half-warps own contiguous
// halves of the edge range and process edge PAIRS: HADD2 the two fp16 rows,
// then convert and accumulate with add.rn.f32x2. ----
__global__ __launch_bounds__(256) void prop_kernel(int layer, int N, int zero_deg) {
    int gw   = (blockIdx.x * blockDim.x + threadIdx.x) >> 5;
    int lane = threadIdx.x & 31;
    if (gw >= N) return;
    const uint4* __restrict__ uin  = (layer == 0) ? g_u0 : (layer == 1) ? g_u1 : g_u2;
    uint4* __restrict__       uout = (layer == 0) ? g_u1 : (layer == 1) ? g_u2 : g_u3;
    int start = g_off[gw];
    int d     = g_deg[gw];
    int half  = lane >> 4;
    int l16   = lane & 15;
    int mid   = start + (d >> 1);
    int s0 = half ? mid : start;
    int e0 = half ? (start + d) : mid;

    unsigned long long acc0 = 0ull, acc1 = 0ull, acc2 = 0ull, acc3 = 0ull;
    int e = s0;
#pragma unroll 2
    for (; e + 1 < e0; e += 2) {
        int c0 = __ldg(&g_col[e]);
        int c1 = __ldg(&g_col[e + 1]);
        uint4 v0 = __ldg(&uin[c0 * 16 + l16]);
        uint4 v1 = __ldg(&uin[c1 * 16 + l16]);
        __half2 s0h = __hadd2(H2REF(v0.x), H2REF(v1.x));
        __half2 s1h = __hadd2(H2REF(v0.y), H2REF(v1.y));
        __half2 s2h = __hadd2(H2REF(v0.z), H2REF(v1.z));
        __half2 s3h = __hadd2(H2REF(v0.w), H2REF(v1.w));
        acc0 = add2(acc0, h2f2(s0h));
        acc1 = add2(acc1, h2f2(s1h));
        acc2 = add2(acc2, h2f2(s2h));
        acc3 = add2(acc3, h2f2(s3h));
    }
    if (e < e0) {
        int c0 = __ldg(&g_col[e]);
        uint4 v0 = __ldg(&uin[c0 * 16 + l16]);
        acc0 = add2(acc0, h2f2(H2REF(v0.x)));
        acc1 = add2(acc1, h2f2(H2REF(v0.y)));
        acc2 = add2(acc2, h2f2(H2REF(v0.z)));
        acc3 = add2(acc3, h2f2(H2REF(v0.w)));
    }

    float2 f0 = unpack2(acc0);
    float2 f1 = unpack2(acc1);
    float2 f2 = unpack2(acc2);
    float2 f3 = unpack2(acc3);
    float a[8] = { f0.x, f0.y, f1.x, f1.y, f2.x, f2.y, f3.x, f3.y };
#pragma unroll
    for (int i = 0; i < 8; i++) a[i] += __shfl_xor_sync(0xffffffffu, a[i], 16);
    float di = g_dinv[gw];
    float s = di * di;
    if (half == 0) {
        float f[8];
#pragma unroll
        for (int i = 0; i < 8; i++) f[i] = s * a[i];
        uout[gw * 16 + l16] = pack8h(f);
    }
    if (zero_deg && lane == 0) g_deg[gw] = 0;   // restore invariant for next replay
}

// ---- head phase 1 (R8-proven): t[i] = z_i @ W1half, 4 rows/warp, f32x2 FMAs.
// z values duplicated as (z,z) u64 in smem; k-loop does LDS broadcast + 2 fma2
// per (row,k). W row loaded once per k as ulonglong2 (LDG.128). ----
__global__ __launch_bounds__(256) void head1_kernel(
    const void* __restrict__ nid,
    const float4* __restrict__ emb,
    const float* __restrict__ w1,      // (256,128) row-major
    int b, int rows7)
{
    __shared__ unsigned long long sz[8 * 4 * 128];   // 32 KB: [warp][row][k]
    int lane = threadIdx.x & 31;
    int wib  = threadIdx.x >> 5;                     // warp in block
    int warp = (blockIdx.x * blockDim.x + threadIdx.x) >> 5;
    int row0 = warp * 4;
    if (row0 >= rows7) return;
    int is32 = g_is32;
    int nvalid = min(4, rows7 - row0);
    unsigned long long* szw = sz + wib * 512;

    const uint2* u1v = reinterpret_cast<const uint2*>(g_u1);
    const uint2* u2v = reinterpret_cast<const uint2*>(g_u2);
    const uint2* u3v = reinterpret_cast<const uint2*>(g_u3);

    int koffr[4];
#pragma unroll
    for (int r = 0; r < 4; r++) {
        int row = row0 + ((r < nvalid) ? r : (nvalid - 1));
        koffr[r] = (row < b) ? 0 : 128;
        int node = ld_idx(nid, row, is32);
        float4 e = __ldg(&emb[node * 32 + lane]);
        uint2 v1 = __ldg(&u1v[node * 32 + lane]);
        uint2 v2 = __ldg(&u2v[node * 32 + lane]);
        uint2 v3 = __ldg(&u3v[node * 32 + lane]);
        float sd = __ldg(&g_sdeg[node]);
        float2 a0 = __half22float2(H2REF(v1.x));
        float2 a1 = __half22float2(H2REF(v1.y));
        float2 b0 = __half22float2(H2REF(v2.x));
        float2 b1_ = __half22float2(H2REF(v2.y));
        float2 c0 = __half22float2(H2REF(v3.x));
        float2 c1 = __half22float2(H2REF(v3.y));
        float z0 = 0.25f * (e.x + sd * (a0.x + b0.x + c0.x));
        float z1 = 0.25f * (e.y + sd * (a0.y + b0.y + c0.y));
        float z2 = 0.25f * (e.z + sd * (a1.x + b1_.x + c1.x));
        float z3 = 0.25f * (e.w + sd * (a1.y + b1_.y + c1.y));
        szw[r * 128 + lane * 4 + 0] = pack2(z0, z0);
        szw[r * 128 + lane * 4 + 1] = pack2(z1, z1);
        szw[r * 128 + lane * 4 + 2] = pack2(z2, z2);
        szw[r * 128 + lane * 4 + 3] = pack2(z3, z3);
    }
    __syncwarp();

    unsigned long long acc[4][2];
#pragma unroll
    for (int r = 0; r < 4; r++) { acc[r][0] = 0ull; acc[r][1] = 0ull; }

    const ulonglong2* wll = reinterpret_cast<const ulonglong2*>(w1);
    bool uni = (koffr[0] == koffr[3]);

    if (uni) {
        int koff = koffr[0];
#pragma unroll 4
        for (int k = 0; k < 128; k++) {
            ulonglong2 wv = __ldg(&wll[(koff + k) * 32 + lane]);
#pragma unroll
            for (int r = 0; r < 4; r++) {
                unsigned long long z2 = szw[r * 128 + k];
                acc[r][0] = fma2(wv.x, z2, acc[r][0]);
                acc[r][1] = fma2(wv.y, z2, acc[r][1]);
            }
        }
    } else {
#pragma unroll 2
        for (int k = 0; k < 128; k++) {
#pragma unroll
            for (int r = 0; r < 4; r++) {
                ulonglong2 wv = __ldg(&wll[(koffr[r] + k) * 32 + lane]);
                unsigned long long z2 = szw[r * 128 + k];
                acc[r][0] = fma2(wv.x, z2, acc[r][0]);
                acc[r][1] = fma2(wv.y, z2, acc[r][1]);
            }
        }
    }

#pragma unroll
    for (int r = 0; r < 4; r++) {
        if (r >= nvalid) break;
        float2 a0 = unpack2(acc[r][0]);
        float2 a1 = unpack2(acc[r][1]);
        // lane covers output cols lane*4 .. lane*4+3 -> float4 at index lane
        g_t[(row0 + r) * 32 + lane] = make_float4(a0.x, a0.y, a1.x, a1.y);
    }
}

// ---- head phase 2: combine t rows -> logits ----
__global__ __launch_bounds__(256) void head2_kernel(
    const float* __restrict__ b1,
    const float* __restrict__ w2,
    const float* __restrict__ b2,
    float* __restrict__ out,
    int b, int total)
{
    int lane = threadIdx.x & 31;
    int warp = (blockIdx.x * blockDim.x + threadIdx.x) >> 5;
    int row0 = warp * 4;
    if (row0 >= total) return;
    float4 b1v = __ldg((const float4*)b1 + lane);
    float4 w2v = __ldg((const float4*)w2 + lane);
    float bias2 = __ldg(b2);
    int nvalid = min(4, total - row0);
    for (int r = 0; r < nvalid; r++) {
        int row = row0 + r;
        int i1, i2;
        if (row < b) { i1 = row; i2 = b + row; }
        else { int j = row - b; i1 = j / 5; i2 = 2 * b + j; }
        float4 ta = __ldg(&g_t[i1 * 32 + lane]);
        float4 tb = __ldg(&g_t[i2 * 32 + lane]);
        float4 h;
        h.x = ta.x + tb.x + b1v.x;
        h.y = ta.y + tb.y + b1v.y;
        h.z = ta.z + tb.z + b1v.z;
        h.w = ta.w + tb.w + b1v.w;
        h.x = (h.x > 0.f) ? h.x : 0.2f * h.x;
        h.y = (h.y > 0.f) ? h.y : 0.2f * h.y;
        h.z = (h.z > 0.f) ? h.z : 0.2f * h.z;
        h.w = (h.w > 0.f) ? h.w : 0.2f * h.w;
        float p = h.x * w2v.x + h.y * w2v.y + h.z * w2v.z + h.w * w2v.w;
#pragma unroll
        for (int off = 16; off; off >>= 1) p += __shfl_xor_sync(0xffffffffu, p, off);
        if (lane == 0) out[row] = p + bias2;
    }
}

extern "C" void kernel_launch(void* const* d_in, const int* in_sizes, int n_in,
                              void* d_out, int out_size) {
    // Order: x, edge_index, edge_weight, n_id, [neg_sample_num], id_embed, w1, b1, w2, b2
    const void* eidx = d_in[1];
    int E = in_sizes[1] / 2;
    const void* nid = d_in[3];
    int base = (n_in >= 10) ? 5 : 4;
    const float* emb = (const float*)d_in[base];
    const float* w1  = (const float*)d_in[base + 1];
    const float* b1  = (const float*)d_in[base + 2];
    const float* w2  = (const float*)d_in[base + 3];
    const float* b2  = (const float*)d_in[base + 4];
    int N = in_sizes[base] / 128;
    int b = in_sizes[3] / 7;
    if (b > B_MAX) b = B_MAX;
    int rows7 = b * 7;
    int total = b * 6;
    float* out = (float*)d_out;
    (void)out_size;

    if (N > NN) N = NN;
    if (E > EE) E = EE;

    int nblk = (N + 1023) / 1024;      // <= 49 (co-resident on 148 SMs)
    int n16 = N * 16;
    int simax = (E > n16) ? E : n16;

    hist_kernel<<<(E + 255) / 256, 256>>>(eidx, E);
    scan_fused_kernel<<<nblk, 256>>>(N, nblk);
    scatter_init_kernel<<<(simax + 255) / 256, 256>>>(eidx, (const float4*)emb, E, n16);

    for (int layer = 0; layer < 3; layer++) {
        prop_kernel<<<(N + 7) / 8, 256>>>(layer, N, layer == 2);
    }

    int h1blocks = ((rows7 + 3) / 4 + 7) / 8;
    head1_kernel<<<h1blocks, 256>>>(nid, (const float4*)emb, w1, b, rows7);
    int h2blocks = ((total + 3) / 4 + 7) / 8;
    head2_kernel<<<h2blocks, 256>>>(b1, w2, b2, out, b, total);
}

// round 11
// speedup vs baseline: 1.1260x; 1.0464x over previous
#include <cuda_runtime.h>
#include <cuda_fp16.h>

// Problem constants (LightGCN_56538949484988)
#define NN 50000           // nodes
#define EE 800000          // edges
#define B_MAX 4096
#define ROWS7_MAX (7 * B_MAX)

// ---------------- device scratch (no allocations allowed) ----------------
__device__ int    g_is32;
__device__ int    g_scan_done;
__device__ int    g_deg[NN];       // zero-initialized; re-zeroed by last prop layer
__device__ int    g_off[NN];
__device__ int    g_cur[NN];
__device__ int    g_col[EE];       // BYTE offsets (col*256) into u arrays
__device__ float  g_dinv[NN];
__device__ float  g_sdeg[NN];
__device__ int    g_bsum[64];
// u_k = dinv^2 * gathered-sum, fp16. 16 uint4 (=128 halves) per node.
__device__ uint4  g_u0[NN * 16];
__device__ uint4  g_u1[NN * 16];
__device__ uint4  g_u2[NN * 16];
__device__ uint4  g_u3[NN * 16];
// head phase-1 output: t[i] = z_i @ W1half (fp32, 128/row)
__device__ float4 g_t[ROWS7_MAX * 32];

__device__ __forceinline__ int ld_idx(const void* p, long long i, int is32) {
    if (is32) return ((const int*)p)[i];
    return (int)((const long long*)p)[i];
}

__device__ __forceinline__ uint4 pack8h(const float* f) {
    __half2 h0 = __floats2half2_rn(f[0], f[1]);
    __half2 h1 = __floats2half2_rn(f[2], f[3]);
    __half2 h2 = __floats2half2_rn(f[4], f[5]);
    __half2 h3 = __floats2half2_rn(f[6], f[7]);
    uint4 r;
    r.x = *reinterpret_cast<unsigned*>(&h0);
    r.y = *reinterpret_cast<unsigned*>(&h1);
    r.z = *reinterpret_cast<unsigned*>(&h2);
    r.w = *reinterpret_cast<unsigned*>(&h3);
    return r;
}

// ---- packed fp32x2 (Blackwell PTX) ----
__device__ __forceinline__ unsigned long long pack2(float a, float b) {
    unsigned long long r;
    asm("mov.b64 %0, {%1, %2};" : "=l"(r) : "f"(a), "f"(b));
    return r;
}
__device__ __forceinline__ unsigned long long fma2(unsigned long long a,
                                                   unsigned long long b,
                                                   unsigned long long c) {
    unsigned long long d;
    asm("fma.rn.f32x2 %0, %1, %2, %3;" : "=l"(d) : "l"(a), "l"(b), "l"(c));
    return d;
}
__device__ __forceinline__ float2 unpack2(unsigned long long v) {
    float x, y;
    asm("mov.b64 {%0, %1}, %2;" : "=f"(x), "=f"(y) : "l"(v));
    return make_float2(x, y);
}
#define H2REF(u) (*reinterpret_cast<__half2*>(&(u)))

// ---- hist (+inline dtype detect, + reset scan counter) ----
__global__ __launch_bounds__(256) void hist_kernel(const void* __restrict__ eidx, int E) {
    __shared__ int sflag;
    int t = threadIdx.x;
    if (t == 0) sflag = 0;
    __syncthreads();
    if (t < 64) {
        long long v = ((const long long*)eidx)[t];
        if (v < 0 || v >= (long long)NN) sflag = 1;   // benign race
    }
    __syncthreads();
    int is32 = sflag;
    if (blockIdx.x == 0 && t == 0) { g_is32 = is32; g_scan_done = 0; }
    int e = blockIdx.x * blockDim.x + t;
    if (e >= E) return;
    int r = ld_idx(eidx, e, is32);
    atomicAdd(&g_deg[r], 1);
}

// ---- fused 3-phase scan: one kernel, <=64 co-resident blocks ----
__global__ __launch_bounds__(256) void scan_fused_kernel(int N, int nblk) {
    __shared__ int wsum[8];
    __shared__ int sred[2];
    int bid = blockIdx.x, t = threadIdx.x;
    int i0 = bid * 1024 + t * 4;
    int d0 = 0, d1 = 0, d2 = 0, d3 = 0;
    if (i0 + 0 < N) d0 = g_deg[i0 + 0];
    if (i0 + 1 < N) d1 = g_deg[i0 + 1];
    if (i0 + 2 < N) d2 = g_deg[i0 + 2];
    if (i0 + 3 < N) d3 = g_deg[i0 + 3];
    int tsum = d0 + d1 + d2 + d3;
    int lane = t & 31, w = t >> 5;
    int x = tsum;
#pragma unroll
    for (int o = 1; o < 32; o <<= 1) {
        int y = __shfl_up_sync(0xffffffffu, x, o);
        if (lane >= o) x += y;
    }
    if (lane == 31) wsum[w] = x;
    __syncthreads();
    int wpref = 0, btotal = 0;
#pragma unroll
    for (int j = 0; j < 8; j++) {
        int v = wsum[j];
        if (j < w) wpref += v;
        btotal += v;
    }
    if (t == 0) {
        g_bsum[bid] = btotal;
        __threadfence();
        atomicAdd(&g_scan_done, 1);
        while (*(volatile int*)&g_scan_done < nblk) { }
    }
    __syncthreads();
    int pv = (t < 64 && t < bid) ? __ldcg(&g_bsum[t]) : 0;
    if (t < 64) {
#pragma unroll
        for (int o = 16; o; o >>= 1) pv += __shfl_xor_sync(0xffffffffu, pv, o);
        if ((t & 31) == 0) sred[t >> 5] = pv;
    }
    __syncthreads();
    int boff = sred[0] + sred[1];
    int excl = x - tsum + wpref + boff;
    int o0 = excl, o1 = o0 + d0, o2 = o1 + d1, o3 = o2 + d2;
#define EMIT(ii, oo, dd) \
    if (ii < N) { g_off[ii] = oo; g_cur[ii] = oo; \
        g_dinv[ii] = (dd) > 0 ? rsqrtf((float)(dd)) : 0.f; \
        g_sdeg[ii] = sqrtf((float)(dd)); }
    EMIT(i0 + 0, o0, d0)
    EMIT(i0 + 1, o1, d1)
    EMIT(i0 + 2, o2, d2)
    EMIT(i0 + 3, o3, d3)
#undef EMIT
}

// ---- fused scatter (CSR fill, byte offsets) + init (u0 = fp16(dinv .* emb)) ----
__global__ __launch_bounds__(256) void scatter_init_kernel(
    const void* __restrict__ eidx, const float4* __restrict__ emb, int E, int N16)
{
    int i = blockIdx.x * blockDim.x + threadIdx.x;
    int is32 = g_is32;
    if (i < E) {
        int r = ld_idx(eidx, i, is32);
        int c = ld_idx(eidx, (long long)E + i, is32);
        int p = atomicAdd(&g_cur[r], 1);
        g_col[p] = c << 8;             // byte offset: 256 B per node row
    }
    if (i < N16) {
        int node = i >> 4, p = i & 15;
        float4 a = emb[node * 32 + p * 2];
        float4 b = emb[node * 32 + p * 2 + 1];
        float di = g_dinv[node];
        float f[8] = { a.x * di, a.y * di, a.z * di, a.w * di,
                       b.x * di, b.y * di, b.z * di, b.w * di };
        g_u0[i] = pack8h(f);
    }
}

// ---- one propagation layer: warp/node; half-warps own contiguous halves of
// the edge range; edge PAIRS with full-fp16 accumulation (HADD2 only in the
// loop); convert to fp32 once per node for the cross-half reduction. ----
__global__ __launch_bounds__(256) void prop_kernel(int layer, int N, int zero_deg) {
    int gw   = (blockIdx.x * blockDim.x + threadIdx.x) >> 5;
    int lane = threadIdx.x & 31;
    if (gw >= N) return;
    const uint4* __restrict__ uin  = (layer == 0) ? g_u0 : (layer == 1) ? g_u1 : g_u2;
    uint4* __restrict__       uout = (layer == 0) ? g_u1 : (layer == 1) ? g_u2 : g_u3;
    int start = g_off[gw];
    int d     = g_deg[gw];
    int half  = lane >> 4;
    int l16   = lane & 15;
    int mid   = start + (d >> 1);
    int s0 = half ? mid : start;
    int e0 = half ? (start + d) : mid;

    const char* ubase = (const char*)uin + l16 * 16;

    __half2 a0 = __floats2half2_rn(0.f, 0.f);
    __half2 a1 = a0, a2 = a0, a3 = a0;
    int e = s0;
#pragma unroll 2
    for (; e + 1 < e0; e += 2) {
        int c0 = __ldg(&g_col[e]);
        int c1 = __ldg(&g_col[e + 1]);
        uint4 v0 = __ldg((const uint4*)(ubase + c0));
        uint4 v1 = __ldg((const uint4*)(ubase + c1));
        a0 = __hadd2(a0, __hadd2(H2REF(v0.x), H2REF(v1.x)));
        a1 = __hadd2(a1, __hadd2(H2REF(v0.y), H2REF(v1.y)));
        a2 = __hadd2(a2, __hadd2(H2REF(v0.z), H2REF(v1.z)));
        a3 = __hadd2(a3, __hadd2(H2REF(v0.w), H2REF(v1.w)));
    }
    if (e < e0) {
        int c0 = __ldg(&g_col[e]);
        uint4 v0 = __ldg((const uint4*)(ubase + c0));
        a0 = __hadd2(a0, H2REF(v0.x));
        a1 = __hadd2(a1, H2REF(v0.y));
        a2 = __hadd2(a2, H2REF(v0.z));
        a3 = __hadd2(a3, H2REF(v0.w));
    }

    float2 f0 = __half22float2(a0);
    float2 f1 = __half22float2(a1);
    float2 f2 = __half22float2(a2);
    float2 f3 = __half22float2(a3);
    float a[8] = { f0.x, f0.y, f1.x, f1.y, f2.x, f2.y, f3.x, f3.y };
#pragma unroll
    for (int i = 0; i < 8; i++) a[i] += __shfl_xor_sync(0xffffffffu, a[i], 16);
    float di = g_dinv[gw];
    float s = di * di;
    if (half == 0) {
        float f[8];
#pragma unroll
        for (int i = 0; i < 8; i++) f[i] = s * a[i];
        uout[gw * 16 + l16] = pack8h(f);
    }
    if (zero_deg && lane == 0) g_deg[gw] = 0;   // restore invariant for next replay
}

// ---- head phase 1 (R8-proven): t[i] = z_i @ W1half, 4 rows/warp, f32x2 FMAs.
// z values duplicated as (z,z) u64 in smem; k-loop does LDS broadcast + 2 fma2
// per (row,k). W row loaded once per k as ulonglong2 (LDG.128). ----
__global__ __launch_bounds__(256) void head1_kernel(
    const void* __restrict__ nid,
    const float4* __restrict__ emb,
    const float* __restrict__ w1,      // (256,128) row-major
    int b, int rows7)
{
    __shared__ unsigned long long sz[8 * 4 * 128];   // 32 KB: [warp][row][k]
    int lane = threadIdx.x & 31;
    int wib  = threadIdx.x >> 5;                     // warp in block
    int warp = (blockIdx.x * blockDim.x + threadIdx.x) >> 5;
    int row0 = warp * 4;
    if (row0 >= rows7) return;
    int is32 = g_is32;
    int nvalid = min(4, rows7 - row0);
    unsigned long long* szw = sz + wib * 512;

    const uint2* u1v = reinterpret_cast<const uint2*>(g_u1);
    const uint2* u2v = reinterpret_cast<const uint2*>(g_u2);
    const uint2* u3v = reinterpret_cast<const uint2*>(g_u3);

    int koffr[4];
#pragma unroll
    for (int r = 0; r < 4; r++) {
        int row = row0 + ((r < nvalid) ? r : (nvalid - 1));
        koffr[r] = (row < b) ? 0 : 128;
        int node = ld_idx(nid, row, is32);
        float4 e = __ldg(&emb[node * 32 + lane]);
        uint2 v1 = __ldg(&u1v[node * 32 + lane]);
        uint2 v2 = __ldg(&u2v[node * 32 + lane]);
        uint2 v3 = __ldg(&u3v[node * 32 + lane]);
        float sd = __ldg(&g_sdeg[node]);
        float2 a0 = __half22float2(H2REF(v1.x));
        float2 a1 = __half22float2(H2REF(v1.y));
        float2 b0 = __half22float2(H2REF(v2.x));
        float2 b1_ = __half22float2(H2REF(v2.y));
        float2 c0 = __half22float2(H2REF(v3.x));
        float2 c1 = __half22float2(H2REF(v3.y));
        float z0 = 0.25f * (e.x + sd * (a0.x + b0.x + c0.x));
        float z1 = 0.25f * (e.y + sd * (a0.y + b0.y + c0.y));
        float z2 = 0.25f * (e.z + sd * (a1.x + b1_.x + c1.x));
        float z3 = 0.25f * (e.w + sd * (a1.y + b1_.y + c1.y));
        szw[r * 128 + lane * 4 + 0] = pack2(z0, z0);
        szw[r * 128 + lane * 4 + 1] = pack2(z1, z1);
        szw[r * 128 + lane * 4 + 2] = pack2(z2, z2);
        szw[r * 128 + lane * 4 + 3] = pack2(z3, z3);
    }
    __syncwarp();

    unsigned long long acc[4][2];
#pragma unroll
    for (int r = 0; r < 4; r++) { acc[r][0] = 0ull; acc[r][1] = 0ull; }

    const ulonglong2* wll = reinterpret_cast<const ulonglong2*>(w1);
    bool uni = (koffr[0] == koffr[3]);

    if (uni) {
        int koff = koffr[0];
#pragma unroll 4
        for (int k = 0; k < 128; k++) {
            ulonglong2 wv = __ldg(&wll[(koff + k) * 32 + lane]);
#pragma unroll
            for (int r = 0; r < 4; r++) {
                unsigned long long z2 = szw[r * 128 + k];
                acc[r][0] = fma2(wv.x, z2, acc[r][0]);
                acc[r][1] = fma2(wv.y, z2, acc[r][1]);
            }
        }
    } else {
#pragma unroll 2
        for (int k = 0; k < 128; k++) {
#pragma unroll
            for (int r = 0; r < 4; r++) {
                ulonglong2 wv = __ldg(&wll[(koffr[r] + k) * 32 + lane]);
                unsigned long long z2 = szw[r * 128 + k];
                acc[r][0] = fma2(wv.x, z2, acc[r][0]);
                acc[r][1] = fma2(wv.y, z2, acc[r][1]);
            }
        }
    }

#pragma unroll
    for (int r = 0; r < 4; r++) {
        if (r >= nvalid) break;
        float2 a0 = unpack2(acc[r][0]);
        float2 a1 = unpack2(acc[r][1]);
        g_t[(row0 + r) * 32 + lane] = make_float4(a0.x, a0.y, a1.x, a1.y);
    }
}

// ---- head phase 2: combine t rows -> logits ----
__global__ __launch_bounds__(256) void head2_kernel(
    const float* __restrict__ b1,
    const float* __restrict__ w2,
    const float* __restrict__ b2,
    float* __restrict__ out,
    int b, int total)
{
    int lane = threadIdx.x & 31;
    int warp = (blockIdx.x * blockDim.x + threadIdx.x) >> 5;
    int row0 = warp * 4;
    if (row0 >= total) return;
    float4 b1v = __ldg((const float4*)b1 + lane);
    float4 w2v = __ldg((const float4*)w2 + lane);
    float bias2 = __ldg(b2);
    int nvalid = min(4, total - row0);
    for (int r = 0; r < nvalid; r++) {
        int row = row0 + r;
        int i1, i2;
        if (row < b) { i1 = row; i2 = b + row; }
        else { int j = row - b; i1 = j / 5; i2 = 2 * b + j; }
        float4 ta = __ldg(&g_t[i1 * 32 + lane]);
        float4 tb = __ldg(&g_t[i2 * 32 + lane]);
        float4 h;
        h.x = ta.x + tb.x + b1v.x;
        h.y = ta.y + tb.y + b1v.y;
        h.z = ta.z + tb.z + b1v.z;
        h.w = ta.w + tb.w + b1v.w;
        h.x = (h.x > 0.f) ? h.x : 0.2f * h.x;
        h.y = (h.y > 0.f) ? h.y : 0.2f * h.y;
        h.z = (h.z > 0.f) ? h.z : 0.2f * h.z;
        h.w = (h.w > 0.f) ? h.w : 0.2f * h.w;
        float p = h.x * w2v.x + h.y * w2v.y + h.z * w2v.z + h.w * w2v.w;
#pragma unroll
        for (int off = 16; off; off >>= 1) p += __shfl_xor_sync(0xffffffffu, p, off);
        if (lane == 0) out[row] = p + bias2;
    }
}

extern "C" void kernel_launch(void* const* d_in, const int* in_sizes, int n_in,
                              void* d_out, int out_size) {
    // Order: x, edge_index, edge_weight, n_id, [neg_sample_num], id_embed, w1, b1, w2, b2
    const void* eidx = d_in[1];
    int E = in_sizes[1] / 2;
    const void* nid = d_in[3];
    int base = (n_in >= 10) ? 5 : 4;
    const float* emb = (const float*)d_in[base];
    const float* w1  = (const float*)d_in[base + 1];
    const float* b1  = (const float*)d_in[base + 2];
    const float* w2  = (const float*)d_in[base + 3];
    const float* b2  = (const float*)d_in[base + 4];
    int N = in_sizes[base] / 128;
    int b = in_sizes[3] / 7;
    if (b > B_MAX) b = B_MAX;
    int rows7 = b * 7;
    int total = b * 6;
    float* out = (float*)d_out;
    (void)out_size;

    if (N > NN) N = NN;
    if (E > EE) E = EE;

    int nblk = (N + 1023) / 1024;      // <= 49 (co-resident on 148 SMs)
    int n16 = N * 16;
    int simax = (E > n16) ? E : n16;

    hist_kernel<<<(E + 255) / 256, 256>>>(eidx, E);
    scan_fused_kernel<<<nblk, 256>>>(N, nblk);
    scatter_init_kernel<<<(simax + 255) / 256, 256>>>(eidx, (const float4*)emb, E, n16);

    for (int layer = 0; layer < 3; layer++) {
        prop_kernel<<<(N + 7) / 8, 256>>>(layer, N, layer == 2);
    }

    int h1blocks = ((rows7 + 3) / 4 + 7) / 8;
    head1_kernel<<<h1blocks, 256>>>(nid, (const float4*)emb, w1, b, rows7);
    int h2blocks = ((total + 3) / 4 + 7) / 8;
    head2_kernel<<<h2blocks, 256>>>(b1, w2, b2, out, b, total);
}

// round 12
// speedup vs baseline: 1.1444x; 1.0163x over previous
#include <cuda_runtime.h>
#include <cuda_fp16.h>

// Problem constants (LightGCN_56538949484988)
#define NN 50000           // nodes
#define EE 800000          // edges
#define B_MAX 4096
#define ROWS7_MAX (7 * B_MAX)

// ---------------- device scratch (no allocations allowed) ----------------
__device__ int    g_is32;
__device__ int    g_scan_done;
__device__ int    g_deg[NN];       // zero-initialized; re-zeroed by last prop layer
__device__ int    g_off[NN];
__device__ int    g_cur[NN];
__device__ int    g_col[EE];       // BYTE offsets (col*256) into u arrays
__device__ float  g_dinv[NN];
__device__ float  g_sdeg[NN];
__device__ int    g_bsum[64];
// u_k = dinv^2 * gathered-sum, fp16. 16 uint4 (=128 halves) per node.
__device__ uint4  g_u0[NN * 16];
__device__ uint4  g_u1[NN * 16];
__device__ uint4  g_u2[NN * 16];
__device__ uint4  g_u3[NN * 16];
// head phase-1 output: t[i] = z_i @ W1half (fp32, 128/row)
__device__ float4 g_t[ROWS7_MAX * 32];

__device__ __forceinline__ int ld_idx(const void* p, long long i, int is32) {
    if (is32) return ((const int*)p)[i];
    return (int)((const long long*)p)[i];
}

__device__ __forceinline__ uint4 pack8h(const float* f) {
    __half2 h0 = __floats2half2_rn(f[0], f[1]);
    __half2 h1 = __floats2half2_rn(f[2], f[3]);
    __half2 h2 = __floats2half2_rn(f[4], f[5]);
    __half2 h3 = __floats2half2_rn(f[6], f[7]);
    uint4 r;
    r.x = *reinterpret_cast<unsigned*>(&h0);
    r.y = *reinterpret_cast<unsigned*>(&h1);
    r.z = *reinterpret_cast<unsigned*>(&h2);
    r.w = *reinterpret_cast<unsigned*>(&h3);
    return r;
}

// ---- packed fp32x2 (Blackwell PTX) ----
__device__ __forceinline__ unsigned long long pack2(float a, float b) {
    unsigned long long r;
    asm("mov.b64 %0, {%1, %2};" : "=l"(r) : "f"(a), "f"(b));
    return r;
}
__device__ __forceinline__ unsigned long long fma2(unsigned long long a,
                                                   unsigned long long b,
                                                   unsigned long long c) {
    unsigned long long d;
    asm("fma.rn.f32x2 %0, %1, %2, %3;" : "=l"(d) : "l"(a), "l"(b), "l"(c));
    return d;
}
__device__ __forceinline__ float2 unpack2(unsigned long long v) {
    float x, y;
    asm("mov.b64 {%0, %1}, %2;" : "=f"(x), "=f"(y) : "l"(v));
    return make_float2(x, y);
}
#define H2REF(u) (*reinterpret_cast<__half2*>(&(u)))

// ---- hist (+inline dtype detect, + reset scan counter) ----
__global__ __launch_bounds__(256) void hist_kernel(const void* __restrict__ eidx, int E) {
    __shared__ int sflag;
    int t = threadIdx.x;
    if (t == 0) sflag = 0;
    __syncthreads();
    if (t < 64) {
        long long v = ((const long long*)eidx)[t];
        if (v < 0 || v >= (long long)NN) sflag = 1;   // benign race
    }
    __syncthreads();
    int is32 = sflag;
    if (blockIdx.x == 0 && t == 0) { g_is32 = is32; g_scan_done = 0; }
    int e = blockIdx.x * blockDim.x + t;
    if (e >= E) return;
    int r = ld_idx(eidx, e, is32);
    atomicAdd(&g_deg[r], 1);
}

// ---- fused 3-phase scan: one kernel, <=64 co-resident blocks ----
__global__ __launch_bounds__(256) void scan_fused_kernel(int N, int nblk) {
    __shared__ int wsum[8];
    __shared__ int sred[2];
    int bid = blockIdx.x, t = threadIdx.x;
    int i0 = bid * 1024 + t * 4;
    int d0 = 0, d1 = 0, d2 = 0, d3 = 0;
    if (i0 + 0 < N) d0 = g_deg[i0 + 0];
    if (i0 + 1 < N) d1 = g_deg[i0 + 1];
    if (i0 + 2 < N) d2 = g_deg[i0 + 2];
    if (i0 + 3 < N) d3 = g_deg[i0 + 3];
    int tsum = d0 + d1 + d2 + d3;
    int lane = t & 31, w = t >> 5;
    int x = tsum;
#pragma unroll
    for (int o = 1; o < 32; o <<= 1) {
        int y = __shfl_up_sync(0xffffffffu, x, o);
        if (lane >= o) x += y;
    }
    if (lane == 31) wsum[w] = x;
    __syncthreads();
    int wpref = 0, btotal = 0;
#pragma unroll
    for (int j = 0; j < 8; j++) {
        int v = wsum[j];
        if (j < w) wpref += v;
        btotal += v;
    }
    if (t == 0) {
        g_bsum[bid] = btotal;
        __threadfence();
        atomicAdd(&g_scan_done, 1);
        while (*(volatile int*)&g_scan_done < nblk) { }
    }
    __syncthreads();
    int pv = (t < 64 && t < bid) ? __ldcg(&g_bsum[t]) : 0;
    if (t < 64) {
#pragma unroll
        for (int o = 16; o; o >>= 1) pv += __shfl_xor_sync(0xffffffffu, pv, o);
        if ((t & 31) == 0) sred[t >> 5] = pv;
    }
    __syncthreads();
    int boff = sred[0] + sred[1];
    int excl = x - tsum + wpref + boff;
    int o0 = excl, o1 = o0 + d0, o2 = o1 + d1, o3 = o2 + d2;
#define EMIT(ii, oo, dd) \
    if (ii < N) { g_off[ii] = oo; g_cur[ii] = oo; \
        g_dinv[ii] = (dd) > 0 ? rsqrtf((float)(dd)) : 0.f; \
        g_sdeg[ii] = sqrtf((float)(dd)); }
    EMIT(i0 + 0, o0, d0)
    EMIT(i0 + 1, o1, d1)
    EMIT(i0 + 2, o2, d2)
    EMIT(i0 + 3, o3, d3)
#undef EMIT
}

// ---- fused scatter (CSR fill, byte offsets) + init (u0 = fp16(dinv .* emb)) ----
__global__ __launch_bounds__(256) void scatter_init_kernel(
    const void* __restrict__ eidx, const float4* __restrict__ emb, int E, int N16)
{
    int i = blockIdx.x * blockDim.x + threadIdx.x;
    int is32 = g_is32;
    if (i < E) {
        int r = ld_idx(eidx, i, is32);
        int c = ld_idx(eidx, (long long)E + i, is32);
        int p = atomicAdd(&g_cur[r], 1);
        g_col[p] = c << 8;             // byte offset: 256 B per node row
    }
    if (i < N16) {
        int node = i >> 4, p = i & 15;
        float4 a = emb[node * 32 + p * 2];
        float4 b = emb[node * 32 + p * 2 + 1];
        float di = g_dinv[node];
        float f[8] = { a.x * di, a.y * di, a.z * di, a.w * di,
                       b.x * di, b.y * di, b.z * di, b.w * di };
        g_u0[i] = pack8h(f);
    }
}

// ---- one propagation layer: warp/node; 32 lanes x uint2 (8B) per row; whole
// warp walks the edge range in 4-edge quads (MLP=4 at low register cost);
// full-fp16 accumulation with a 2-level HADD2 tree; no cross-lane reduce. ----
__global__ __launch_bounds__(256) void prop_kernel(int layer, int N, int zero_deg) {
    int gw   = (blockIdx.x * blockDim.x + threadIdx.x) >> 5;
    int lane = threadIdx.x & 31;
    if (gw >= N) return;
    const uint4* __restrict__ uin4  = (layer == 0) ? g_u0 : (layer == 1) ? g_u1 : g_u2;
    uint2* __restrict__       uout  = (uint2*)((layer == 0) ? g_u1 : (layer == 1) ? g_u2 : g_u3);
    int e   = g_off[gw];
    int d   = g_deg[gw];
    int end = e + d;

    const char* ubase = (const char*)uin4 + lane * 8;

    __half2 a0 = __floats2half2_rn(0.f, 0.f);
    __half2 a1 = a0;
    for (; e + 3 < end; e += 4) {
        int c0 = __ldg(&g_col[e]);
        int c1 = __ldg(&g_col[e + 1]);
        int c2 = __ldg(&g_col[e + 2]);
        int c3 = __ldg(&g_col[e + 3]);
        uint2 v0 = __ldg((const uint2*)(ubase + c0));
        uint2 v1 = __ldg((const uint2*)(ubase + c1));
        uint2 v2 = __ldg((const uint2*)(ubase + c2));
        uint2 v3 = __ldg((const uint2*)(ubase + c3));
        __half2 s0 = __hadd2(__hadd2(H2REF(v0.x), H2REF(v1.x)),
                             __hadd2(H2REF(v2.x), H2REF(v3.x)));
        __half2 s1 = __hadd2(__hadd2(H2REF(v0.y), H2REF(v1.y)),
                             __hadd2(H2REF(v2.y), H2REF(v3.y)));
        a0 = __hadd2(a0, s0);
        a1 = __hadd2(a1, s1);
    }
    if (e + 1 < end) {
        int c0 = __ldg(&g_col[e]);
        int c1 = __ldg(&g_col[e + 1]);
        uint2 v0 = __ldg((const uint2*)(ubase + c0));
        uint2 v1 = __ldg((const uint2*)(ubase + c1));
        a0 = __hadd2(a0, __hadd2(H2REF(v0.x), H2REF(v1.x)));
        a1 = __hadd2(a1, __hadd2(H2REF(v0.y), H2REF(v1.y)));
        e += 2;
    }
    if (e < end) {
        int c0 = __ldg(&g_col[e]);
        uint2 v0 = __ldg((const uint2*)(ubase + c0));
        a0 = __hadd2(a0, H2REF(v0.x));
        a1 = __hadd2(a1, H2REF(v0.y));
    }

    float2 f0 = __half22float2(a0);
    float2 f1 = __half22float2(a1);
    float di = g_dinv[gw];
    float s = di * di;
    __half2 h0 = __floats2half2_rn(s * f0.x, s * f0.y);
    __half2 h1 = __floats2half2_rn(s * f1.x, s * f1.y);
    uint2 o;
    o.x = *reinterpret_cast<unsigned*>(&h0);
    o.y = *reinterpret_cast<unsigned*>(&h1);
    uout[gw * 32 + lane] = o;
    if (zero_deg && lane == 0) g_deg[gw] = 0;   // restore invariant for next replay
}

// ---- head phase 1 (R8-proven): t[i] = z_i @ W1half, 4 rows/warp, f32x2 FMAs.
// z values duplicated as (z,z) u64 in smem; k-loop does LDS broadcast + 2 fma2
// per (row,k). W row loaded once per k as ulonglong2 (LDG.128). ----
__global__ __launch_bounds__(256) void head1_kernel(
    const void* __restrict__ nid,
    const float4* __restrict__ emb,
    const float* __restrict__ w1,      // (256,128) row-major
    int b, int rows7)
{
    __shared__ unsigned long long sz[8 * 4 * 128];   // 32 KB: [warp][row][k]
    int lane = threadIdx.x & 31;
    int wib  = threadIdx.x >> 5;                     // warp in block
    int warp = (blockIdx.x * blockDim.x + threadIdx.x) >> 5;
    int row0 = warp * 4;
    if (row0 >= rows7) return;
    int is32 = g_is32;
    int nvalid = min(4, rows7 - row0);
    unsigned long long* szw = sz + wib * 512;

    const uint2* u1v = reinterpret_cast<const uint2*>(g_u1);
    const uint2* u2v = reinterpret_cast<const uint2*>(g_u2);
    const uint2* u3v = reinterpret_cast<const uint2*>(g_u3);

    int koffr[4];
#pragma unroll
    for (int r = 0; r < 4; r++) {
        int row = row0 + ((r < nvalid) ? r : (nvalid - 1));
        koffr[r] = (row < b) ? 0 : 128;
        int node = ld_idx(nid, row, is32);
        float4 e = __ldg(&emb[node * 32 + lane]);
        uint2 v1 = __ldg(&u1v[node * 32 + lane]);
        uint2 v2 = __ldg(&u2v[node * 32 + lane]);
        uint2 v3 = __ldg(&u3v[node * 32 + lane]);
        float sd = __ldg(&g_sdeg[node]);
        float2 a0 = __half22float2(H2REF(v1.x));
        float2 a1 = __half22float2(H2REF(v1.y));
        float2 b0 = __half22float2(H2REF(v2.x));
        float2 b1_ = __half22float2(H2REF(v2.y));
        float2 c0 = __half22float2(H2REF(v3.x));
        float2 c1 = __half22float2(H2REF(v3.y));
        float z0 = 0.25f * (e.x + sd * (a0.x + b0.x + c0.x));
        float z1 = 0.25f * (e.y + sd * (a0.y + b0.y + c0.y));
        float z2 = 0.25f * (e.z + sd * (a1.x + b1_.x + c1.x));
        float z3 = 0.25f * (e.w + sd * (a1.y + b1_.y + c1.y));
        szw[r * 128 + lane * 4 + 0] = pack2(z0, z0);
        szw[r * 128 + lane * 4 + 1] = pack2(z1, z1);
        szw[r * 128 + lane * 4 + 2] = pack2(z2, z2);
        szw[r * 128 + lane * 4 + 3] = pack2(z3, z3);
    }
    __syncwarp();

    unsigned long long acc[4][2];
#pragma unroll
    for (int r = 0; r < 4; r++) { acc[r][0] = 0ull; acc[r][1] = 0ull; }

    const ulonglong2* wll = reinterpret_cast<const ulonglong2*>(w1);
    bool uni = (koffr[0] == koffr[3]);

    if (uni) {
        int koff = koffr[0];
#pragma unroll 4
        for (int k = 0; k < 128; k++) {
            ulonglong2 wv = __ldg(&wll[(koff + k) * 32 + lane]);
#pragma unroll
            for (int r = 0; r < 4; r++) {
                unsigned long long z2 = szw[r * 128 + k];
                acc[r][0] = fma2(wv.x, z2, acc[r][0]);
                acc[r][1] = fma2(wv.y, z2, acc[r][1]);
            }
        }
    } else {
#pragma unroll 2
        for (int k = 0; k < 128; k++) {
#pragma unroll
            for (int r = 0; r < 4; r++) {
                ulonglong2 wv = __ldg(&wll[(koffr[r] + k) * 32 + lane]);
                unsigned long long z2 = szw[r * 128 + k];
                acc[r][0] = fma2(wv.x, z2, acc[r][0]);
                acc[r][1] = fma2(wv.y, z2, acc[r][1]);
            }
        }
    }

#pragma unroll
    for (int r = 0; r < 4; r++) {
        if (r >= nvalid) break;
        float2 a0 = unpack2(acc[r][0]);
        float2 a1 = unpack2(acc[r][1]);
        g_t[(row0 + r) * 32 + lane] = make_float4(a0.x, a0.y, a1.x, a1.y);
    }
}

// ---- head phase 2: combine t rows -> logits ----
__global__ __launch_bounds__(256) void head2_kernel(
    const float* __restrict__ b1,
    const float* __restrict__ w2,
    const float* __restrict__ b2,
    float* __restrict__ out,
    int b, int total)
{
    int lane = threadIdx.x & 31;
    int warp = (blockIdx.x * blockDim.x + threadIdx.x) >> 5;
    int row0 = warp * 4;
    if (row0 >= total) return;
    float4 b1v = __ldg((const float4*)b1 + lane);
    float4 w2v = __ldg((const float4*)w2 + lane);
    float bias2 = __ldg(b2);
    int nvalid = min(4, total - row0);
    for (int r = 0; r < nvalid; r++) {
        int row = row0 + r;
        int i1, i2;
        if (row < b) { i1 = row; i2 = b + row; }
        else { int j = row - b; i1 = j / 5; i2 = 2 * b + j; }
        float4 ta = __ldg(&g_t[i1 * 32 + lane]);
        float4 tb = __ldg(&g_t[i2 * 32 + lane]);
        float4 h;
        h.x = ta.x + tb.x + b1v.x;
        h.y = ta.y + tb.y + b1v.y;
        h.z = ta.z + tb.z + b1v.z;
        h.w = ta.w + tb.w + b1v.w;
        h.x = (h.x > 0.f) ? h.x : 0.2f * h.x;
        h.y = (h.y > 0.f) ? h.y : 0.2f * h.y;
        h.z = (h.z > 0.f) ? h.z : 0.2f * h.z;
        h.w = (h.w > 0.f) ? h.w : 0.2f * h.w;
        float p = h.x * w2v.x + h.y * w2v.y + h.z * w2v.z + h.w * w2v.w;
#pragma unroll
        for (int off = 16; off; off >>= 1) p += __shfl_xor_sync(0xffffffffu, p, off);
        if (lane == 0) out[row] = p + bias2;
    }
}

extern "C" void kernel_launch(void* const* d_in, const int* in_sizes, int n_in,
                              void* d_out, int out_size) {
    // Order: x, edge_index, edge_weight, n_id, [neg_sample_num], id_embed, w1, b1, w2, b2
    const void* eidx = d_in[1];
    int E = in_sizes[1] / 2;
    const void* nid = d_in[3];
    int base = (n_in >= 10) ? 5 : 4;
    const float* emb = (const float*)d_in[base];
    const float* w1  = (const float*)d_in[base + 1];
    const float* b1  = (const float*)d_in[base + 2];
    const float* w2  = (const float*)d_in[base + 3];
    const float* b2  = (const float*)d_in[base + 4];
    int N = in_sizes[base] / 128;
    int b = in_sizes[3] / 7;
    if (b > B_MAX) b = B_MAX;
    int rows7 = b * 7;
    int total = b * 6;
    float* out = (float*)d_out;
    (void)out_size;

    if (N > NN) N = NN;
    if (E > EE) E = EE;

    int nblk = (N + 1023) / 1024;      // <= 49 (co-resident on 148 SMs)
    int n16 = N * 16;
    int simax = (E > n16) ? E : n16;

    hist_kernel<<<(E + 255) / 256, 256>>>(eidx, E);
    scan_fused_kernel<<<nblk, 256>>>(N, nblk);
    scatter_init_kernel<<<(simax + 255) / 256, 256>>>(eidx, (const float4*)emb, E, n16);

    for (int layer = 0; layer < 3; layer++) {
        prop_kernel<<<(N + 7) / 8, 256>>>(layer, N, layer == 2);
    }

    int h1blocks = ((rows7 + 3) / 4 + 7) / 8;
    head1_kernel<<<h1blocks, 256>>>(nid, (const float4*)emb, w1, b, rows7);
    int h2blocks = ((total + 3) / 4 + 7) / 8;
    head2_kernel<<<h2blocks, 256>>>(b1, w2, b2, out, b, total);
}